// round 1
// baseline (speedup 1.0000x reference)
#include <cuda_runtime.h>
#include <cstdint>

// Problem constants
// inputs: [32, 256, 32, 32] f32   (B, C, H, W), C = emb_dim = 256
// embed : [256, 1024] f32         (emb_dim, num_emb)
// N = B*H*W = 32768 flattened positions, K = 1024 codewords
// Output layout (concat, f32): quantize_st [32,256,32,32] (8388608), loss (1),
//                              onehot [32768,1024] (33554432)  => 41943041 total

#define NPOS   32768
#define KEMB   1024
#define CDIM   256
#define QELEMS 8388608   // 32*256*32*32

__device__ float g_esqh[KEMB];     // 0.5 * sum_c embed[c][k]^2
__device__ int   g_idx[NPOS];      // argmin index per position
__device__ float g_loss;           // sum of squared diffs

// ---------------------------------------------------------------------------
// cp.async helpers
// ---------------------------------------------------------------------------
__device__ __forceinline__ void cp16(void* smem, const void* gptr) {
    uint32_t s = (uint32_t)__cvta_generic_to_shared(smem);
    asm volatile("cp.async.ca.shared.global [%0], [%1], 16;" :: "r"(s), "l"(gptr));
}
__device__ __forceinline__ void cp_commit() {
    asm volatile("cp.async.commit_group;");
}
template <int N>
__device__ __forceinline__ void cp_wait() {
    asm volatile("cp.async.wait_group %0;" :: "n"(N));
}

// ---------------------------------------------------------------------------
// Kernel 1: per-codeword 0.5*||e_k||^2, and reset loss accumulator
// ---------------------------------------------------------------------------
__global__ void k_esq(const float* __restrict__ emb) {
    int k = blockIdx.x * 256 + threadIdx.x;   // grid 4 x 256 covers 1024
    float s = 0.f;
    #pragma unroll 8
    for (int c = 0; c < CDIM; ++c) {
        float e = emb[c * KEMB + k];
        s = fmaf(e, e, s);
    }
    g_esqh[k] = 0.5f * s;
    if (k == 0) g_loss = 0.f;
}

// ---------------------------------------------------------------------------
// Kernel 2: distance GEMM + running argmin.
// Block tile: 128 positions x 128 codewords per k-iteration, 8 k-iterations.
// Threads 256 as 16x16; micro-tile 8x8 with split rows/cols {t*4, 64+t*4}.
// score(n,k) = 0.5*||e_k||^2 - x_n . e_k   (same argmin as squared distance)
// ---------------------------------------------------------------------------
__global__ __launch_bounds__(256, 2) void k_argmin(const float* __restrict__ inp,
                                                   const float* __restrict__ emb) {
    const int tid = threadIdx.x;
    const int tx = tid & 15;
    const int ty = tid >> 4;

    const int n0  = blockIdx.x * 128;          // 256 blocks, tiles never cross b
    const int b   = n0 >> 10;
    const int hw0 = n0 & 1023;
    const float* Xp = inp + (size_t)b * (CDIM * 1024) + hw0;  // X[c][nn] = Xp[c*1024+nn]

    __shared__ float Xs[2][16][128];
    __shared__ float Es[2][16][128];

    float bv[8];
    int   bi[8];
    #pragma unroll
    for (int i = 0; i < 8; ++i) { bv[i] = 3.4e38f; bi[i] = 0; }

    // loader mapping: each thread loads 2 float4 per tile array
    const int lc = tid >> 5;          // 0..7
    const int lq = (tid & 31) * 4;    // 0..124

    for (int ko = 0; ko < 8; ++ko) {
        const int k0 = ko * 128;

        float acc[8][8];
        #pragma unroll
        for (int i = 0; i < 8; ++i)
            #pragma unroll
            for (int j = 0; j < 8; ++j) acc[i][j] = 0.f;

        // prefetch chunk 0
        cp16(&Xs[0][lc    ][lq], Xp  + (size_t)(lc    ) * 1024 + lq);
        cp16(&Xs[0][lc + 8][lq], Xp  + (size_t)(lc + 8) * 1024 + lq);
        cp16(&Es[0][lc    ][lq], emb + (size_t)(lc    ) * 1024 + k0 + lq);
        cp16(&Es[0][lc + 8][lq], emb + (size_t)(lc + 8) * 1024 + k0 + lq);
        cp_commit();

        int buf = 0;
        for (int cc = 0; cc < 16; ++cc) {
            if (cc < 15) {
                const int c0 = (cc + 1) * 16;
                const int nb = buf ^ 1;
                cp16(&Xs[nb][lc    ][lq], Xp  + (size_t)(c0 + lc    ) * 1024 + lq);
                cp16(&Xs[nb][lc + 8][lq], Xp  + (size_t)(c0 + lc + 8) * 1024 + lq);
                cp16(&Es[nb][lc    ][lq], emb + (size_t)(c0 + lc    ) * 1024 + k0 + lq);
                cp16(&Es[nb][lc + 8][lq], emb + (size_t)(c0 + lc + 8) * 1024 + k0 + lq);
                cp_commit();
                cp_wait<1>();
            } else {
                cp_wait<0>();
            }
            __syncthreads();

            #pragma unroll
            for (int c = 0; c < 16; ++c) {
                float a[8], bb[8];
                *(float4*)&a[0]  = *(const float4*)&Xs[buf][c][ty * 4];
                *(float4*)&a[4]  = *(const float4*)&Xs[buf][c][64 + ty * 4];
                *(float4*)&bb[0] = *(const float4*)&Es[buf][c][tx * 4];
                *(float4*)&bb[4] = *(const float4*)&Es[buf][c][64 + tx * 4];
                #pragma unroll
                for (int i = 0; i < 8; ++i)
                    #pragma unroll
                    for (int j = 0; j < 8; ++j)
                        acc[i][j] = fmaf(a[i], bb[j], acc[i][j]);
            }
            __syncthreads();
            buf ^= 1;
        }

        // scoring + running argmin update
        #pragma unroll
        for (int j = 0; j < 8; ++j) {
            const int k = k0 + ((j < 4) ? (tx * 4 + j) : (64 + tx * 4 + (j - 4)));
            const float eh = g_esqh[k];
            #pragma unroll
            for (int i = 0; i < 8; ++i) {
                float v = eh - acc[i][j];
                if (v < bv[i] || (v == bv[i] && k < bi[i])) { bv[i] = v; bi[i] = k; }
            }
        }
    }

    // reduce across the 16 tx-lanes sharing the same rows (xor stays in 16-group)
    #pragma unroll
    for (int i = 0; i < 8; ++i) {
        float v = bv[i];
        int   k = bi[i];
        #pragma unroll
        for (int off = 8; off; off >>= 1) {
            float ov = __shfl_xor_sync(0xffffffffu, v, off);
            int   ok = __shfl_xor_sync(0xffffffffu, k, off);
            if (ov < v || (ov == v && ok < k)) { v = ov; k = ok; }
        }
        if (tx == 0) {
            const int r = (i < 4) ? (ty * 4 + i) : (64 + ty * 4 + (i - 4));
            g_idx[n0 + r] = k;
        }
    }
}

// ---------------------------------------------------------------------------
// Kernel 3: quantize gather + loss partial sums.
// out_q[b,c,hw] = embed[c][idx[b*1024+hw]]; loss += (e - x)^2
// grid: 32 b * 8 hw-chunks = 256 blocks, 128 threads (one hw each)
// ---------------------------------------------------------------------------
__global__ void k_quant(const float* __restrict__ inp, const float* __restrict__ emb,
                        float* __restrict__ outq) {
    const int t   = threadIdx.x;
    const int blk = blockIdx.x;
    const int b   = blk >> 3;
    const int hw  = (blk & 7) * 128 + t;
    const int n   = b * 1024 + hw;
    const int idx = g_idx[n];
    const size_t base = (size_t)b * (CDIM * 1024) + hw;

    float ls = 0.f;
    #pragma unroll 4
    for (int c = 0; c < CDIM; ++c) {
        float x = inp[base + (size_t)c * 1024];
        float e = emb[c * KEMB + idx];
        outq[base + (size_t)c * 1024] = e;
        float d = e - x;
        ls = fmaf(d, d, ls);
    }

    __shared__ float red[128];
    red[t] = ls;
    __syncthreads();
    #pragma unroll
    for (int s = 64; s; s >>= 1) {
        if (t < s) red[t] += red[t + s];
        __syncthreads();
    }
    if (t == 0) atomicAdd(&g_loss, red[0]);
}

// ---------------------------------------------------------------------------
// Kernel 4: onehot fill (zeros + one) and loss scalar write.
// onehot base offset is 8388609 (odd -> scalar stores).
// grid 4096 blocks x 256 threads; 8 rows per block.
// ---------------------------------------------------------------------------
__global__ void k_onehot(float* __restrict__ d_out) {
    float* oh = d_out + (QELEMS + 1);
    const int t  = threadIdx.x;
    const int r0 = blockIdx.x * 8;
    #pragma unroll
    for (int rr = 0; rr < 8; ++rr) {
        const int n   = r0 + rr;
        const int idx = g_idx[n];
        const size_t base = (size_t)n * KEMB;
        #pragma unroll
        for (int p = 0; p < 4; ++p) {
            const int j = t + p * 256;
            oh[base + j] = (j == idx) ? 1.0f : 0.0f;
        }
    }
    if (blockIdx.x == 0 && t == 0) {
        d_out[QELEMS] = 1.25f * g_loss / (float)QELEMS;
    }
}

// ---------------------------------------------------------------------------
extern "C" void kernel_launch(void* const* d_in, const int* in_sizes, int n_in,
                              void* d_out, int out_size) {
    const float* inp = (const float*)d_in[0];
    const float* emb = (const float*)d_in[1];
    float* out = (float*)d_out;

    k_esq<<<4, 256>>>(emb);
    k_argmin<<<256, 256>>>(inp, emb);
    k_quant<<<256, 128>>>(inp, emb, out);
    k_onehot<<<4096, 256>>>(out);
}

// round 4
// speedup vs baseline: 1.0495x; 1.0495x over previous
#include <cuda_runtime.h>
#include <cuda_bf16.h>
#include <cstdint>

// VQ argmin: 32768 positions x 1024 codewords, C=256.
// inputs [32,256,32,32] f32, embed [256,1024] f32.
// out = concat(quantize_st [8388608], loss [1], onehot [33554432]) f32.

#define NPOS   32768
#define KEMB   1024
#define CDIM   256
#define QELEMS 8388608

// ---------------------------------------------------------------------------
// device scratch
// ---------------------------------------------------------------------------
__device__ __align__(256) __nv_bfloat16 g_Xhi[NPOS * CDIM];
__device__ __align__(256) __nv_bfloat16 g_Xlo[NPOS * CDIM];
__device__ __align__(256) __nv_bfloat16 g_Ehi[KEMB * CDIM];
__device__ __align__(256) __nv_bfloat16 g_Elo[KEMB * CDIM];
__device__ float g_esqh[KEMB];
__device__ int   g_idx[NPOS];
__device__ float g_loss;
__device__ int   g_nrep;
__device__ int   g_rep[NPOS];
// per-(kblock, position) partial top-2
__device__ float g_p1[8 * NPOS];
__device__ float g_p2[8 * NPOS];
__device__ int   g_pk[8 * NPOS];

// ---------------------------------------------------------------------------
// helpers
// ---------------------------------------------------------------------------
__device__ __forceinline__ uint32_t s2u(const void* p) {
    uint32_t a;
    asm("{ .reg .u64 t; cvta.to.shared.u64 t, %1; cvt.u32.u64 %0, t; }" : "=r"(a) : "l"(p));
    return a;
}
__device__ __forceinline__ void cp16(uint32_t s, const void* g) {
    asm volatile("cp.async.cg.shared.global [%0], [%1], 16;" :: "r"(s), "l"(g));
}
__device__ __forceinline__ void cpcommit() { asm volatile("cp.async.commit_group;"); }
template <int N>
__device__ __forceinline__ void cpwait() { asm volatile("cp.async.wait_group %0;" :: "n"(N)); }

__device__ __forceinline__ void ldm_x4(uint32_t& r0, uint32_t& r1, uint32_t& r2, uint32_t& r3,
                                       uint32_t addr) {
    asm volatile("ldmatrix.sync.aligned.m8n8.x4.shared.b16 {%0,%1,%2,%3}, [%4];"
                 : "=r"(r0), "=r"(r1), "=r"(r2), "=r"(r3) : "r"(addr));
}
__device__ __forceinline__ void ldm_x2(uint32_t& r0, uint32_t& r1, uint32_t addr) {
    asm volatile("ldmatrix.sync.aligned.m8n8.x2.shared.b16 {%0,%1}, [%2];"
                 : "=r"(r0), "=r"(r1) : "r"(addr));
}
__device__ __forceinline__ void mma16816(float* d, const uint32_t* a, const uint32_t* b) {
    asm volatile(
        "mma.sync.aligned.m16n8k16.row.col.f32.bf16.bf16.f32 "
        "{%0,%1,%2,%3}, {%4,%5,%6,%7}, {%8,%9}, {%0,%1,%2,%3};"
        : "+f"(d[0]), "+f"(d[1]), "+f"(d[2]), "+f"(d[3])
        : "r"(a[0]), "r"(a[1]), "r"(a[2]), "r"(a[3]), "r"(b[0]), "r"(b[1]));
}

// ---------------------------------------------------------------------------
// Kernel: 0.5*||e_k||^2 + counter reset
// ---------------------------------------------------------------------------
__global__ void k_esq(const float* __restrict__ emb) {
    int k = blockIdx.x * 256 + threadIdx.x;
    float s = 0.f;
    #pragma unroll 8
    for (int c = 0; c < CDIM; ++c) {
        float e = emb[c * KEMB + k];
        s = fmaf(e, e, s);
    }
    g_esqh[k] = 0.5f * s;
    if (k == 0) { g_loss = 0.f; g_nrep = 0; }
}

// ---------------------------------------------------------------------------
// Kernel: transpose + bf16 hi/lo split ([256][1024] f32 slices -> [n][256] bf16)
// ---------------------------------------------------------------------------
__global__ void k_split(const float* __restrict__ src, int is_embed) {
    __nv_bfloat16* __restrict__ hi = is_embed ? g_Ehi : g_Xhi;
    __nv_bfloat16* __restrict__ lo = is_embed ? g_Elo : g_Xlo;
    __shared__ float Xs[32][257];
    const int t = threadIdx.x;
    const int s = blockIdx.x >> 5;
    const int hw0 = (blockIdx.x & 31) * 32;
    const int lane = t & 31, w = t >> 5;
    const float* sp = src + (size_t)s * (CDIM * 1024);

    #pragma unroll
    for (int i = 0; i < 32; ++i) {
        int c = w + i * 8;
        Xs[lane][c] = sp[(size_t)c * 1024 + hw0 + lane];
    }
    __syncthreads();

    #pragma unroll
    for (int rr = 0; rr < 4; ++rr) {
        int r = w * 4 + rr;
        size_t ob = ((size_t)s * 1024 + hw0 + r) * CDIM;
        #pragma unroll
        for (int j = 0; j < 8; ++j) {
            int c = lane + 32 * j;
            float x = Xs[r][c];
            __nv_bfloat16 h = __float2bfloat16(x);
            __nv_bfloat16 l = __float2bfloat16(x - __bfloat162float(h));
            hi[ob + c] = h;
            lo[ob + c] = l;
        }
    }
}

// ---------------------------------------------------------------------------
// Kernel: HMMA split-bf16 GEMM tile + per-row top-2.
// Grid 2048: nb = bid>>3 (128 positions), kb = bid&7 (128 codewords).
// Effective C = 768: combos (Xhi,Ehi),(Xlo,Ehi),(Xhi,Elo), 8 BK=32 chunks each.
// 3-stage cp.async pipeline; 8 warps as 2(M) x 4(N); warp tile 64x32.
// ---------------------------------------------------------------------------
#define ROWB   80                 // smem bytes per row (40 bf16, 16B-mult)
#define STG_A  (128 * ROWB)       // 10240
#define STG    (2 * STG_A)        // A+B per stage
#define NCHUNK 24
#define MMA_SMEM (3 * STG)        // 61440

__global__ __launch_bounds__(256, 2) void k_mma() {
    extern __shared__ char dsm[];
    const uint32_t sb = s2u(dsm);
    __shared__ float sEsq[128];
    __shared__ float sv1[4][128];
    __shared__ float sv2[4][128];
    __shared__ int   sk1[4][128];

    const int tid = threadIdx.x;
    const int l   = tid & 31;
    const int wid = tid >> 5;
    const int wm  = wid & 1;       // m-offset 64*wm
    const int wn  = wid >> 1;      // n-offset 32*wn

    const int nb = blockIdx.x >> 3;
    const int kb = blockIdx.x & 7;
    const int n0 = nb * 128;
    const int k0 = kb * 128;

    if (tid < 128) sEsq[tid] = g_esqh[k0 + tid];

    const __nv_bfloat16* Asrc[3] = {
        g_Xhi + (size_t)n0 * CDIM, g_Xlo + (size_t)n0 * CDIM, g_Xhi + (size_t)n0 * CDIM };
    const __nv_bfloat16* Bsrc[3] = {
        g_Ehi + (size_t)k0 * CDIM, g_Ehi + (size_t)k0 * CDIM, g_Elo + (size_t)k0 * CDIM };

    auto load_chunk = [&](int c, int s) {
        const int combo = c >> 3, kk = (c & 7) * 32;
        const __nv_bfloat16* Ag = Asrc[combo] + kk;
        const __nv_bfloat16* Bg = Bsrc[combo] + kk;
        const uint32_t ab = sb + s * STG, bbs = ab + STG_A;
        #pragma unroll
        for (int u = 0; u < 2; ++u) {
            const int idx = tid + u * 256;        // 0..511
            const int row = idx >> 2, q = idx & 3;
            cp16(ab  + row * ROWB + q * 16, Ag + (size_t)row * CDIM + q * 8);
            cp16(bbs + row * ROWB + q * 16, Bg + (size_t)row * CDIM + q * 8);
        }
        cpcommit();
    };

    float acc[4][4][4];
    #pragma unroll
    for (int i = 0; i < 4; ++i)
        #pragma unroll
        for (int j = 0; j < 4; ++j)
            #pragma unroll
            for (int r = 0; r < 4; ++r) acc[i][j][r] = 0.f;

    load_chunk(0, 0);
    load_chunk(1, 1);
    load_chunk(2, 2);

    #pragma unroll 1
    for (int c = 0; c < NCHUNK; ++c) {
        if (c <= NCHUNK - 3)      cpwait<2>();
        else if (c == NCHUNK - 2) cpwait<1>();
        else                      cpwait<0>();
        __syncthreads();

        const int s = c % 3;
        const uint32_t ab = sb + s * STG, bbs = ab + STG_A;
        #pragma unroll
        for (int ks = 0; ks < 2; ++ks) {
            uint32_t afr[4][4], bfr[4][2];
            #pragma unroll
            for (int mt = 0; mt < 4; ++mt)
                ldm_x4(afr[mt][0], afr[mt][1], afr[mt][2], afr[mt][3],
                       ab + (uint32_t)(wm * 64 + mt * 16 + (l & 15)) * ROWB
                          + (uint32_t)(ks * 16 + (l >> 4) * 8) * 2);
            #pragma unroll
            for (int nt = 0; nt < 4; ++nt)
                ldm_x2(bfr[nt][0], bfr[nt][1],
                       bbs + (uint32_t)(wn * 32 + nt * 8 + (l & 7)) * ROWB
                           + (uint32_t)(ks * 16 + ((l >> 3) & 1) * 8) * 2);
            #pragma unroll
            for (int mt = 0; mt < 4; ++mt)
                #pragma unroll
                for (int nt = 0; nt < 4; ++nt)
                    mma16816(acc[mt][nt], afr[mt], bfr[nt]);
        }
        __syncthreads();
        if (c + 3 < NCHUNK) load_chunk(c + 3, s);
    }

    // ---- epilogue: per-row top-2 over this 128-codeword block ----
    #pragma unroll
    for (int mt = 0; mt < 4; ++mt) {
        #pragma unroll
        for (int rr = 0; rr < 2; ++rr) {
            const int rowCTA = wm * 64 + mt * 16 + (l >> 2) + rr * 8;
            float v1 = 3.4e38f, v2 = 3.4e38f;
            int   k1 = 0;
            #pragma unroll
            for (int nt = 0; nt < 4; ++nt) {
                #pragma unroll
                for (int cc = 0; cc < 2; ++cc) {
                    const int col = wn * 32 + nt * 8 + (l & 3) * 2 + cc;
                    const float v = sEsq[col] - acc[mt][nt][rr * 2 + cc];
                    if (v < v1)      { v2 = v1; v1 = v; k1 = k0 + col; }
                    else if (v < v2) { v2 = v; }
                }
            }
            #pragma unroll
            for (int off = 1; off <= 2; off <<= 1) {
                const float ov1 = __shfl_xor_sync(0xffffffffu, v1, off);
                const float ov2 = __shfl_xor_sync(0xffffffffu, v2, off);
                const int   ok1 = __shfl_xor_sync(0xffffffffu, k1, off);
                if (ov1 < v1 || (ov1 == v1 && ok1 < k1)) {
                    v2 = fminf(v1, ov2); v1 = ov1; k1 = ok1;
                } else {
                    v2 = fminf(v2, ov1);
                }
            }
            if ((l & 3) == 0) {
                sv1[wn][rowCTA] = v1; sv2[wn][rowCTA] = v2; sk1[wn][rowCTA] = k1;
            }
        }
    }
    __syncthreads();
    if (tid < 128) {
        float v1 = sv1[0][tid], v2 = sv2[0][tid];
        int   k1 = sk1[0][tid];
        #pragma unroll
        for (int w = 1; w < 4; ++w) {
            const float pv1 = sv1[w][tid], pv2 = sv2[w][tid];
            const int   pk  = sk1[w][tid];
            if (pv1 < v1 || (pv1 == v1 && pk < k1)) {
                v2 = fminf(v1, pv2); v1 = pv1; k1 = pk;
            } else {
                v2 = fminf(v2, pv1);
            }
        }
        g_p1[kb * NPOS + n0 + tid] = v1;
        g_p2[kb * NPOS + n0 + tid] = v2;
        g_pk[kb * NPOS + n0 + tid] = k1;
    }
}

// ---------------------------------------------------------------------------
// Kernel: combine 8 k-block partials -> argmin + repair flags
// ---------------------------------------------------------------------------
__global__ void k_final() {
    const int n = blockIdx.x * 256 + threadIdx.x;
    float v1 = 3.4e38f, v2 = 3.4e38f;
    int k1 = 0x7fffffff;
    #pragma unroll
    for (int kb = 0; kb < 8; ++kb) {
        const float pv1 = g_p1[kb * NPOS + n];
        const float pv2 = g_p2[kb * NPOS + n];
        const int   pk  = g_pk[kb * NPOS + n];
        if (pv1 < v1 || (pv1 == v1 && pk < k1)) {
            v2 = fminf(v1, pv2); v1 = pv1; k1 = pk;
        } else {
            v2 = fminf(v2, pv1);
        }
    }
    g_idx[n] = k1;
    if (v2 - v1 < 4e-3f) {
        int slot = atomicAdd(&g_nrep, 1);
        g_rep[slot] = n;
    }
}

// ---------------------------------------------------------------------------
// Kernel: exact fp32 re-argmin for flagged near-tie positions
// ---------------------------------------------------------------------------
__global__ void k_repair(const float* __restrict__ inp, const float* __restrict__ emb) {
    __shared__ float xs[256];
    __shared__ float rv[256];
    __shared__ int   rk[256];
    const int t = threadIdx.x;
    const int nrep = g_nrep;
    for (int i = blockIdx.x; i < nrep; i += gridDim.x) {
        const int n = g_rep[i];
        const int b = n >> 10, hw = n & 1023;
        xs[t] = inp[(size_t)b * (CDIM * 1024) + (size_t)t * 1024 + hw];
        __syncthreads();
        float best = 3.4e38f; int bk = 0x7fffffff;
        #pragma unroll 1
        for (int kk = 0; kk < 4; ++kk) {
            const int k = t + kk * 256;
            float dot = 0.f;
            #pragma unroll 8
            for (int c = 0; c < CDIM; ++c) dot = fmaf(xs[c], emb[c * KEMB + k], dot);
            const float v = g_esqh[k] - dot;
            if (v < best || (v == best && k < bk)) { best = v; bk = k; }
        }
        rv[t] = best; rk[t] = bk;
        __syncthreads();
        for (int s = 128; s; s >>= 1) {
            if (t < s) {
                if (rv[t + s] < rv[t] || (rv[t + s] == rv[t] && rk[t + s] < rk[t])) {
                    rv[t] = rv[t + s]; rk[t] = rk[t + s];
                }
            }
            __syncthreads();
        }
        if (t == 0) g_idx[n] = rk[0];
        __syncthreads();
    }
}

// ---------------------------------------------------------------------------
// Kernel: quantize gather + loss partials
// ---------------------------------------------------------------------------
__global__ void k_quant(const float* __restrict__ inp, const float* __restrict__ emb,
                        float* __restrict__ outq) {
    const int t   = threadIdx.x;
    const int blk = blockIdx.x;
    const int b   = blk >> 3;
    const int hw  = (blk & 7) * 128 + t;
    const int n   = b * 1024 + hw;
    const int idx = g_idx[n];
    const size_t base = (size_t)b * (CDIM * 1024) + hw;

    float ls = 0.f;
    #pragma unroll 4
    for (int c = 0; c < CDIM; ++c) {
        float x = inp[base + (size_t)c * 1024];
        float e = emb[c * KEMB + idx];
        outq[base + (size_t)c * 1024] = e;
        float d = e - x;
        ls = fmaf(d, d, ls);
    }
    __shared__ float red[128];
    red[t] = ls;
    __syncthreads();
    #pragma unroll
    for (int s = 64; s; s >>= 1) {
        if (t < s) red[t] += red[t + s];
        __syncthreads();
    }
    if (t == 0) atomicAdd(&g_loss, red[0]);
}

// ---------------------------------------------------------------------------
// Kernel: onehot + loss scalar
// ---------------------------------------------------------------------------
__global__ void k_onehot(float* __restrict__ d_out) {
    float* oh = d_out + (QELEMS + 1);
    const int t  = threadIdx.x;
    const int r0 = blockIdx.x * 8;
    #pragma unroll
    for (int rr = 0; rr < 8; ++rr) {
        const int n   = r0 + rr;
        const int idx = g_idx[n];
        const size_t base = (size_t)n * KEMB;
        #pragma unroll
        for (int p = 0; p < 4; ++p) {
            const int j = t + p * 256;
            oh[base + j] = (j == idx) ? 1.0f : 0.0f;
        }
    }
    if (blockIdx.x == 0 && t == 0) {
        d_out[QELEMS] = 1.25f * g_loss / (float)QELEMS;
    }
}

// ---------------------------------------------------------------------------
extern "C" void kernel_launch(void* const* d_in, const int* in_sizes, int n_in,
                              void* d_out, int out_size) {
    const float* inp = (const float*)d_in[0];
    const float* emb = (const float*)d_in[1];
    float* out = (float*)d_out;

    cudaFuncSetAttribute(k_mma, cudaFuncAttributeMaxDynamicSharedMemorySize, MMA_SMEM);

    k_esq<<<4, 256>>>(emb);
    k_split<<<32, 256>>>(emb, 1);
    k_split<<<1024, 256>>>(inp, 0);
    k_mma<<<2048, 256, MMA_SMEM>>>();
    k_final<<<128, 256>>>();
    k_repair<<<128, 256>>>(inp, emb);
    k_quant<<<256, 128>>>(inp, emb, out);
    k_onehot<<<4096, 256>>>(out);
}